// round 7
// baseline (speedup 1.0000x reference)
#include <cuda_runtime.h>
#include <math.h>

#define NPTS    8192
#define TPB     128
#define QPT     4            // queries per thread
#define QTILE   (TPB*QPT)    // 512 queries per tile
#define NTILE   (NPTS/QTILE) // 16
#define NQUAR   4            // db split
#define QUARPTS (NPTS/NQUAR) // 2048
#define CHUNK   1024         // staged db points per chunk (32 KB dup smem)
#define NBLK    (NTILE*NQUAR*4) // 256

// Scratch (no allocs allowed)
__device__ float        g_pmin[4][NQUAR][NPTS]; // [dir+2*part][quarter][query] = qnorm+min
__device__ unsigned int g_count;                // zero-init; tail resets -> replay-safe

__device__ __forceinline__ unsigned long long pack2(float lo, float hi) {
    unsigned long long r;
    asm("mov.b64 %0, {%1, %2};" : "=l"(r)
        : "r"(__float_as_uint(lo)), "r"(__float_as_uint(hi)));
    return r;
}
__device__ __forceinline__ unsigned long long fma2(unsigned long long a,
                                                   unsigned long long b,
                                                   unsigned long long c) {
    unsigned long long d;
    asm("fma.rn.f32x2 %0, %1, %2, %3;" : "=l"(d) : "l"(a), "l"(b), "l"(c));
    return d;
}
__device__ __forceinline__ void unpack2(unsigned long long v, float& lo, float& hi) {
    unsigned int a, b;
    asm("mov.b64 {%0, %1}, %2;" : "=r"(a), "=r"(b) : "l"(v));
    lo = __uint_as_float(a); hi = __uint_as_float(b);
}

// ---------------------------------------------------------------------------
// grid (NTILE*NQUAR, dir, part), 128 thr. Each thread owns 4 queries (packed
// f32x2 x2), scans its db quarter from duplicated smem, writes qnorm+min to
// g_pmin. Ticket-elected last block reduces quarters -> sqrt -> fp64 sums.
// dir0: query = T@cad, db = cam.  dir1: query = cam, db = T@cad.
// ---------------------------------------------------------------------------
__global__ void __launch_bounds__(TPB, 2)
k_fused(const float* __restrict__ cam, const float* __restrict__ cad,
        const float* __restrict__ xyz, const float* __restrict__ rpy,
        const float* __restrict__ quat, const float* __restrict__ bt,
        const float* __restrict__ theta, const float* __restrict__ pw,
        float* __restrict__ out)
{
    __shared__ ulonglong2 sA[CHUNK];   // (xx, yy): (-2x,-2x),(-2y,-2y)
    __shared__ ulonglong2 sB[CHUNK];   // (zz, ww): (-2z,-2z),(w,w)
    __shared__ float  sxf[12];
    __shared__ double sr0[TPB], sr1[TPB];
    __shared__ int    s_last;

    const int part = blockIdx.z;
    const int dir  = blockIdx.y;
    const int tile = blockIdx.x >> 2;
    const int quar = blockIdx.x & 3;
    const int tid  = threadIdx.x;
    const int dp   = dir + 2 * part;

    // --- per-block transform setup (thread 0; tiny) ---
    if (tid == 0) {
        float qa = quat[0], qb = quat[1], qc = quat[2], qd = quat[3];
        float qn = sqrtf(qa*qa + qb*qb + qc*qc + qd*qd);
        qa /= qn; qb /= qn; qc /= qn; qd /= qn;

        float B[16];
        B[0]  = 1.f - 2.f*qc*qc - 2.f*qd*qd;  B[1]  = 2.f*qb*qc - 2.f*qa*qd;        B[2]  = 2.f*qa*qc + 2.f*qb*qd;        B[3]  = bt[0];
        B[4]  = 2.f*qb*qc + 2.f*qa*qd;        B[5]  = 1.f - 2.f*qb*qb - 2.f*qd*qd;  B[6]  = 2.f*qc*qd - 2.f*qa*qb;        B[7]  = bt[1];
        B[8]  = 2.f*qb*qd - 2.f*qa*qc;        B[9]  = 2.f*qa*qb + 2.f*qc*qd;        B[10] = 1.f - 2.f*qb*qb - 2.f*qc*qc;  B[11] = bt[2];
        B[12] = 0.f; B[13] = 0.f; B[14] = 0.f; B[15] = 1.f;

        float ax = xyz[0], ay = xyz[1], az = xyz[2];
        float u  = rpy[0], v  = rpy[1], w  = rpy[2];
        float th = theta[0];
        float co = cosf(th), si = sinf(th), omc = 1.f - co;

        float R[16];
        R[0]  = u*u + (v*v + w*w)*co;   R[1]  = u*v*omc - w*si;          R[2]  = u*w*omc + v*si;
        R[3]  = (ax*(v*v + w*w) - u*(ay*v + az*w))*omc + (ay*w - az*v)*si;
        R[4]  = u*v*omc + w*si;         R[5]  = v*v + (u*u + w*w)*co;    R[6]  = v*w*omc - u*si;
        R[7]  = (ay*(u*u + w*w) - v*(ax*u + az*w))*omc + (az*u - ax*w)*si;
        R[8]  = u*w*omc - v*si;         R[9]  = v*w*omc + u*si;          R[10] = w*w + (u*u + v*v)*co;
        R[11] = (az*(u*u + v*v) - w*(ax*u + ay*v))*omc + (ax*v - ay*u)*si;
        R[12] = 0.f; R[13] = 0.f; R[14] = 0.f; R[15] = 1.f;

        float T[16];
        #pragma unroll
        for (int r = 0; r < 4; r++)
            #pragma unroll
            for (int c = 0; c < 4; c++) {
                float s = 0.f;
                #pragma unroll
                for (int k = 0; k < 4; k++) s += R[r*4 + k] * B[k*4 + c];
                T[r*4 + c] = s;
            }

        const float* X = (part == 0) ? B : T;
        #pragma unroll
        for (int i = 0; i < 12; i++) sxf[i] = X[i];

        if (blockIdx.x == 0 && dir == 0 && part == 0) {
            // out: [0]=all, [1]=base_obj, [2]=child_obj, [3..18]=base_T, [19..34]=rel_T
            #pragma unroll
            for (int i = 0; i < 16; i++) { out[3 + i] = B[i]; out[19 + i] = R[i]; }
        }
    }
    __syncthreads();

    const float t0 = sxf[0], t1 = sxf[1], t2  = sxf[2],  t3  = sxf[3];
    const float t4 = sxf[4], t5 = sxf[5], t6  = sxf[6],  t7  = sxf[7];
    const float t8 = sxf[8], t9 = sxf[9], t10 = sxf[10], t11 = sxf[11];

    const float* camP = cam + part * NPTS * 3;
    const float* cadP = cad + part * NPTS * 3;

    // --- load 4 queries (tile-local stride TPB) ---
    float qx[QPT], qy[QPT], qz[QPT], qn[QPT];
    #pragma unroll
    for (int k = 0; k < QPT; k++) {
        const int q = tile * QTILE + k * TPB + tid;
        const float* src = (dir == 0) ? cadP : camP;
        float x = src[3*q], y = src[3*q + 1], z = src[3*q + 2];
        if (dir == 0) {
            qx[k] = t0*x + t1*y + t2*z  + t3;
            qy[k] = t4*x + t5*y + t6*z  + t7;
            qz[k] = t8*x + t9*y + t10*z + t11;
        } else { qx[k] = x; qy[k] = y; qz[k] = z; }
        qn[k] = qx[k]*qx[k] + qy[k]*qy[k] + qz[k]*qz[k];
    }
    const unsigned long long qx01 = pack2(qx[0], qx[1]), qx23 = pack2(qx[2], qx[3]);
    const unsigned long long qy01 = pack2(qy[0], qy[1]), qy23 = pack2(qy[2], qy[3]);
    const unsigned long long qz01 = pack2(qz[0], qz[1]), qz23 = pack2(qz[2], qz[3]);

    float m0 = 3.4e38f, m1 = 3.4e38f, m2 = 3.4e38f, m3 = 3.4e38f;

    for (int ch = 0; ch < QUARPTS / CHUNK; ch++) {
        __syncthreads();
        // stage CHUNK db points, duplicated halves, -2 folded in
        for (int j = tid; j < CHUNK; j += TPB) {
            int gj = quar * QUARPTS + ch * CHUNK + j;
            float x, y, z;
            if (dir == 0) {
                x = camP[3*gj]; y = camP[3*gj + 1]; z = camP[3*gj + 2];
            } else {
                float a = cadP[3*gj], b = cadP[3*gj + 1], c = cadP[3*gj + 2];
                x = t0*a + t1*b + t2*c  + t3;
                y = t4*a + t5*b + t6*c  + t7;
                z = t8*a + t9*b + t10*c + t11;
            }
            float w = x*x + y*y + z*z;
            float nx = -2.f*x, ny = -2.f*y, nz = -2.f*z;
            sA[j] = make_ulonglong2(pack2(nx, nx), pack2(ny, ny));
            sB[j] = make_ulonglong2(pack2(nz, nz), pack2(w,  w));
        }
        __syncthreads();

        #pragma unroll 8
        for (int i = 0; i < CHUNK; i++) {
            ulonglong2 a = sA[i];            // a.x = xx, a.y = yy
            ulonglong2 b = sB[i];            // b.x = zz, b.y = ww
            unsigned long long u01 = fma2(qz01, b.x, b.y);
            unsigned long long u23 = fma2(qz23, b.x, b.y);
            u01 = fma2(qy01, a.y, u01);
            u23 = fma2(qy23, a.y, u23);
            u01 = fma2(qx01, a.x, u01);
            u23 = fma2(qx23, a.x, u23);
            float v0, v1, v2, v3;
            unpack2(u01, v0, v1);
            unpack2(u23, v2, v3);
            m0 = fminf(m0, v0);
            m1 = fminf(m1, v1);
            m2 = fminf(m2, v2);
            m3 = fminf(m3, v3);
        }
    }

    // write partial results: qnorm + min (can be tiny-negative; clamped in tail)
    {
        float mm[QPT] = {m0, m1, m2, m3};
        #pragma unroll
        for (int k = 0; k < QPT; k++) {
            const int q = tile * QTILE + k * TPB + tid;
            g_pmin[dp][quar][q] = qn[k] + mm[k];
        }
    }

    // --- ticket: last block reduces everything ---
    __threadfence();
    if (tid == 0) {
        unsigned int ticket = atomicAdd(&g_count, 1u);
        s_last = (ticket == NBLK - 1) ? 1 : 0;
    }
    __syncthreads();
    if (!s_last) return;

    __threadfence();
    double a0 = 0.0, a1 = 0.0;
    for (int i = tid; i < 4 * NPTS; i += TPB) {
        const int d = i >> 13;          // dp
        const int q = i & (NPTS - 1);
        float v = g_pmin[d][0][q];
        v = fminf(v, g_pmin[d][1][q]);
        v = fminf(v, g_pmin[d][2][q]);
        v = fminf(v, g_pmin[d][3][q]);
        double dd = (double)sqrtf(fmaxf(v, 0.f));
        if (d < 2) a0 += dd; else a1 += dd;
    }
    sr0[tid] = a0; sr1[tid] = a1;
    __syncthreads();
    for (int s = TPB / 2; s > 0; s >>= 1) {
        if (tid < s) { sr0[tid] += sr0[tid + s]; sr1[tid] += sr1[tid + s]; }
        __syncthreads();
    }
    if (tid == 0) {
        double obj0 = sr0[0] / (double)NPTS;   // base part
        double obj1 = sr1[0] / (double)NPTS;   // child part
        out[1] = (float)obj0;
        out[2] = (float)obj1;
        out[0] = (float)(((double)pw[0] * obj0 + (double)pw[1] * obj1) / 2.0);
        g_count = 0;   // reset for next graph replay
    }
}

// ---------------------------------------------------------------------------
extern "C" void kernel_launch(void* const* d_in, const int* in_sizes, int n_in,
                              void* d_out, int out_size)
{
    const float* cam  = (const float*)d_in[0];  // camera_pts [2,8192,3]
    const float* cad  = (const float*)d_in[1];  // cad_pts    [2,8192,3]
    const float* xyz  = (const float*)d_in[2];  // [1,3]
    const float* rpy  = (const float*)d_in[3];  // [1,3]
    const float* pw   = (const float*)d_in[4];  // [2]
    const float* quat = (const float*)d_in[5];  // [4]
    const float* bt   = (const float*)d_in[6];  // [3,1]
    const float* th   = (const float*)d_in[7];  // [1]
    float* out = (float*)d_out;

    dim3 grid(NTILE * NQUAR, 2, 2);   // 256 blocks, 2/SM
    k_fused<<<grid, TPB>>>(cam, cad, xyz, rpy, quat, bt, th, pw, out);
}

// round 8
// speedup vs baseline: 1.1703x; 1.1703x over previous
#include <cuda_runtime.h>
#include <math.h>

#define NPTS    8192
#define TPB     256
#define NTILE   (NPTS/TPB)     // 32 query tiles
#define NHALF   2              // db split -> 2 blocks/SM
#define HALFPTS (NPTS/NHALF)   // 4096
#define CHUNK   2048
#define NBLK    (NTILE*NHALF*4) // 256

// Scratch (no allocs allowed)
__device__ float        g_pmin[4][NHALF][NPTS]; // [dir+2*part][half][query] = qnorm+min
__device__ unsigned int g_count;                // zero-init; tail resets -> replay-safe

__device__ __forceinline__ unsigned long long pack2(float lo, float hi) {
    unsigned long long r;
    asm("mov.b64 %0, {%1, %2};" : "=l"(r)
        : "r"(__float_as_uint(lo)), "r"(__float_as_uint(hi)));
    return r;
}
__device__ __forceinline__ unsigned long long fma2(unsigned long long a,
                                                   unsigned long long b,
                                                   unsigned long long c) {
    unsigned long long d;
    asm("fma.rn.f32x2 %0, %1, %2, %3;" : "=l"(d) : "l"(a), "l"(b), "l"(c));
    return d;
}

// ---------------------------------------------------------------------------
// grid (NTILE*NHALF, dir, part) = 256 blocks of 256 thr (2 blocks/SM).
// Same inner loop as the proven 84us kernel (1 query/thread, 2 db pts/iter via
// f32x2); each block scans only half the db. Ticket-elected last block merges
// halves -> sqrt -> fp64 means.
// dir0: query = T@cad, db = cam.  dir1: query = cam, db = T@cad.
// min_j |q-y|^2 = |q|^2 + min_j(|y|^2 - 2 q.y); -2 folded into staged coords.
// ---------------------------------------------------------------------------
__global__ void __launch_bounds__(TPB, 2)
k_fused(const float* __restrict__ cam, const float* __restrict__ cad,
        const float* __restrict__ xyz, const float* __restrict__ rpy,
        const float* __restrict__ quat, const float* __restrict__ bt,
        const float* __restrict__ theta, const float* __restrict__ pw,
        float* __restrict__ out)
{
    __shared__ float4 sxy[CHUNK / 2];   // (-2x0,-2x1,-2y0,-2y1)
    __shared__ float4 szw[CHUNK / 2];   // (-2z0,-2z1,  w0,  w1)
    __shared__ float  sxf[12];
    __shared__ double sr0[TPB], sr1[TPB];
    __shared__ int    s_last;

    const int part = blockIdx.z;
    const int dir  = blockIdx.y;
    const int tile = blockIdx.x >> 1;
    const int half = blockIdx.x & 1;
    const int tid  = threadIdx.x;
    const int dp   = dir + 2 * part;
    const int q    = tile * TPB + tid;

    // --- per-block transform setup (thread 0; tiny) ---
    if (tid == 0) {
        float qa = quat[0], qb = quat[1], qc = quat[2], qd = quat[3];
        float qn = sqrtf(qa*qa + qb*qb + qc*qc + qd*qd);
        qa /= qn; qb /= qn; qc /= qn; qd /= qn;

        float B[16];
        B[0]  = 1.f - 2.f*qc*qc - 2.f*qd*qd;  B[1]  = 2.f*qb*qc - 2.f*qa*qd;        B[2]  = 2.f*qa*qc + 2.f*qb*qd;        B[3]  = bt[0];
        B[4]  = 2.f*qb*qc + 2.f*qa*qd;        B[5]  = 1.f - 2.f*qb*qb - 2.f*qd*qd;  B[6]  = 2.f*qc*qd - 2.f*qa*qb;        B[7]  = bt[1];
        B[8]  = 2.f*qb*qd - 2.f*qa*qc;        B[9]  = 2.f*qa*qb + 2.f*qc*qd;        B[10] = 1.f - 2.f*qb*qb - 2.f*qc*qc;  B[11] = bt[2];
        B[12] = 0.f; B[13] = 0.f; B[14] = 0.f; B[15] = 1.f;

        float ax = xyz[0], ay = xyz[1], az = xyz[2];
        float u  = rpy[0], v  = rpy[1], w  = rpy[2];
        float th = theta[0];
        float co = cosf(th), si = sinf(th), omc = 1.f - co;

        float R[16];
        R[0]  = u*u + (v*v + w*w)*co;   R[1]  = u*v*omc - w*si;          R[2]  = u*w*omc + v*si;
        R[3]  = (ax*(v*v + w*w) - u*(ay*v + az*w))*omc + (ay*w - az*v)*si;
        R[4]  = u*v*omc + w*si;         R[5]  = v*v + (u*u + w*w)*co;    R[6]  = v*w*omc - u*si;
        R[7]  = (ay*(u*u + w*w) - v*(ax*u + az*w))*omc + (az*u - ax*w)*si;
        R[8]  = u*w*omc - v*si;         R[9]  = v*w*omc + u*si;          R[10] = w*w + (u*u + v*v)*co;
        R[11] = (az*(u*u + v*v) - w*(ax*u + ay*v))*omc + (ax*v - ay*u)*si;
        R[12] = 0.f; R[13] = 0.f; R[14] = 0.f; R[15] = 1.f;

        float T[16];
        #pragma unroll
        for (int r = 0; r < 4; r++)
            #pragma unroll
            for (int c = 0; c < 4; c++) {
                float s = 0.f;
                #pragma unroll
                for (int k = 0; k < 4; k++) s += R[r*4 + k] * B[k*4 + c];
                T[r*4 + c] = s;
            }

        const float* X = (part == 0) ? B : T;
        #pragma unroll
        for (int i = 0; i < 12; i++) sxf[i] = X[i];

        if (blockIdx.x == 0 && dir == 0 && part == 0) {
            // out: [0]=all, [1]=base_obj, [2]=child_obj, [3..18]=base_T, [19..34]=rel_T
            #pragma unroll
            for (int i = 0; i < 16; i++) { out[3 + i] = B[i]; out[19 + i] = R[i]; }
        }
    }
    __syncthreads();

    const float t0 = sxf[0], t1 = sxf[1], t2  = sxf[2],  t3  = sxf[3];
    const float t4 = sxf[4], t5 = sxf[5], t6  = sxf[6],  t7  = sxf[7];
    const float t8 = sxf[8], t9 = sxf[9], t10 = sxf[10], t11 = sxf[11];

    const float* camP = cam + part * NPTS * 3;
    const float* cadP = cad + part * NPTS * 3;

    // query point
    float qx, qy, qz;
    {
        const float* src = (dir == 0) ? cadP : camP;
        float x = src[3*q], y = src[3*q + 1], z = src[3*q + 2];
        if (dir == 0) {
            qx = t0*x + t1*y + t2*z  + t3;
            qy = t4*x + t5*y + t6*z  + t7;
            qz = t8*x + t9*y + t10*z + t11;
        } else { qx = x; qy = y; qz = z; }
    }
    const float qnorm = qx*qx + qy*qy + qz*qz;
    const unsigned long long qx2 = pack2(qx, qx);
    const unsigned long long qy2 = pack2(qy, qy);
    const unsigned long long qz2 = pack2(qz, qz);

    float m0 = 3.4e38f, m1 = 3.4e38f;

    for (int ch = 0; ch < HALFPTS / CHUNK; ch++) {
        __syncthreads();
        // stage 2 db points per slot, -2 pre-folded into coords
        for (int jp = tid; jp < CHUNK / 2; jp += TPB) {
            int g0 = half * HALFPTS + ch * CHUNK + 2 * jp;
            float x0, y0, z0, x1, y1, z1;
            if (dir == 0) {
                x0 = camP[3*g0];     y0 = camP[3*g0 + 1]; z0 = camP[3*g0 + 2];
                x1 = camP[3*g0 + 3]; y1 = camP[3*g0 + 4]; z1 = camP[3*g0 + 5];
            } else {
                float a0 = cadP[3*g0],     b0 = cadP[3*g0 + 1], c0 = cadP[3*g0 + 2];
                float a1 = cadP[3*g0 + 3], b1 = cadP[3*g0 + 4], c1 = cadP[3*g0 + 5];
                x0 = t0*a0 + t1*b0 + t2*c0  + t3;   x1 = t0*a1 + t1*b1 + t2*c1  + t3;
                y0 = t4*a0 + t5*b0 + t6*c0  + t7;   y1 = t4*a1 + t5*b1 + t6*c1  + t7;
                z0 = t8*a0 + t9*b0 + t10*c0 + t11;  z1 = t8*a1 + t9*b1 + t10*c1 + t11;
            }
            float w0 = x0*x0 + y0*y0 + z0*z0;
            float w1 = x1*x1 + y1*y1 + z1*z1;
            sxy[jp] = make_float4(-2.f*x0, -2.f*x1, -2.f*y0, -2.f*y1);
            szw[jp] = make_float4(-2.f*z0, -2.f*z1,  w0,      w1);
        }
        __syncthreads();

        #pragma unroll 16
        for (int i = 0; i < CHUNK / 2; i++) {
            ulonglong2 a = *reinterpret_cast<const ulonglong2*>(&sxy[i]); // a.x=xp, a.y=yp
            ulonglong2 b = *reinterpret_cast<const ulonglong2*>(&szw[i]); // b.x=zp, b.y=wp
            unsigned long long t = fma2(qz2, b.x, b.y);   // w - 2 qz*z
            t = fma2(qy2, a.y, t);
            t = fma2(qx2, a.x, t);                        // w - 2 q.y  (both points)
            unsigned int lo, hi;
            asm("mov.b64 {%0, %1}, %2;" : "=r"(lo), "=r"(hi) : "l"(t));
            m0 = fminf(m0, __uint_as_float(lo));
            m1 = fminf(m1, __uint_as_float(hi));
        }
    }

    // partial result for this half (can be tiny-negative; clamped in tail)
    g_pmin[dp][half][q] = qnorm + fminf(m0, m1);

    // --- ticket: last block reduces everything ---
    __threadfence();
    if (tid == 0) {
        unsigned int ticket = atomicAdd(&g_count, 1u);
        s_last = (ticket == NBLK - 1) ? 1 : 0;
    }
    __syncthreads();
    if (!s_last) return;

    __threadfence();
    double a0 = 0.0, a1 = 0.0;
    for (int i = tid; i < 4 * NPTS; i += TPB) {
        const int d  = i >> 13;          // dp
        const int qq = i & (NPTS - 1);
        float v = fminf(g_pmin[d][0][qq], g_pmin[d][1][qq]);
        double dd = (double)sqrtf(fmaxf(v, 0.f));
        if (d < 2) a0 += dd; else a1 += dd;
    }
    sr0[tid] = a0; sr1[tid] = a1;
    __syncthreads();
    for (int s = TPB / 2; s > 0; s >>= 1) {
        if (tid < s) { sr0[tid] += sr0[tid + s]; sr1[tid] += sr1[tid + s]; }
        __syncthreads();
    }
    if (tid == 0) {
        double obj0 = sr0[0] / (double)NPTS;   // base part
        double obj1 = sr1[0] / (double)NPTS;   // child part
        out[1] = (float)obj0;
        out[2] = (float)obj1;
        out[0] = (float)(((double)pw[0] * obj0 + (double)pw[1] * obj1) / 2.0);
        g_count = 0;   // reset for next graph replay
    }
}

// ---------------------------------------------------------------------------
extern "C" void kernel_launch(void* const* d_in, const int* in_sizes, int n_in,
                              void* d_out, int out_size)
{
    const float* cam  = (const float*)d_in[0];  // camera_pts [2,8192,3]
    const float* cad  = (const float*)d_in[1];  // cad_pts    [2,8192,3]
    const float* xyz  = (const float*)d_in[2];  // [1,3]
    const float* rpy  = (const float*)d_in[3];  // [1,3]
    const float* pw   = (const float*)d_in[4];  // [2]
    const float* quat = (const float*)d_in[5];  // [4]
    const float* bt   = (const float*)d_in[6];  // [3,1]
    const float* th   = (const float*)d_in[7];  // [1]
    float* out = (float*)d_out;

    dim3 grid(NTILE * NHALF, 2, 2);   // 256 blocks, 2 per SM
    k_fused<<<grid, TPB>>>(cam, cad, xyz, rpy, quat, bt, th, pw, out);
}

// round 9
// speedup vs baseline: 1.3102x; 1.1195x over previous
#include <cuda_runtime.h>
#include <math.h>

#define NPTS    8192
#define TPB     256
#define QPT     2               // queries per thread (packed f32x2 broadcast)
#define QTILE   (TPB*QPT)       // 512 queries per block
#define NTILE   (NPTS/QTILE)    // 16
#define NHALF   2               // db split
#define HALFPTS (NPTS/NHALF)    // 4096
#define CHUNK   2048
#define NBLK    (NTILE*NHALF*4) // 128 blocks

// Scratch (no allocs allowed)
__device__ float        g_pmin[4][NHALF][NPTS]; // [dir+2*part][half][query] = qnorm+min
__device__ unsigned int g_count;                // zero-init; tail resets -> replay-safe

__device__ __forceinline__ unsigned long long pack2(float lo, float hi) {
    unsigned long long r;
    asm("mov.b64 %0, {%1, %2};" : "=l"(r)
        : "r"(__float_as_uint(lo)), "r"(__float_as_uint(hi)));
    return r;
}
__device__ __forceinline__ unsigned long long fma2(unsigned long long a,
                                                   unsigned long long b,
                                                   unsigned long long c) {
    unsigned long long d;
    asm("fma.rn.f32x2 %0, %1, %2, %3;" : "=l"(d) : "l"(a), "l"(b), "l"(c));
    return d;
}

// ---------------------------------------------------------------------------
// grid (NTILE*NHALF, dir, part) = 128 blocks of 256 thr.
// Each thread owns 2 queries (qA, qB) packed as broadcast f32x2; each iter
// loads 2 db points (R6 pair layout, 2x LDS.128) and evaluates all 4
// (query,point) pairs -> 0.5 LDS per pair (R6 had 1.0; LDS-issue was the bound).
// dir0: query = T@cad, db = cam.  dir1: query = cam, db = T@cad.
// min_j |q-y|^2 = |q|^2 + min_j(|y|^2 - 2 q.y); -2 folded into staged coords.
// Ticket-elected last block merges db halves -> sqrt -> fp64 means.
// ---------------------------------------------------------------------------
__global__ void __launch_bounds__(TPB)
k_fused(const float* __restrict__ cam, const float* __restrict__ cad,
        const float* __restrict__ xyz, const float* __restrict__ rpy,
        const float* __restrict__ quat, const float* __restrict__ bt,
        const float* __restrict__ theta, const float* __restrict__ pw,
        float* __restrict__ out)
{
    __shared__ float4 sxy[CHUNK / 2];   // (-2x0,-2x1,-2y0,-2y1)
    __shared__ float4 szw[CHUNK / 2];   // (-2z0,-2z1,  w0,  w1)
    __shared__ float  sxf[12];
    __shared__ double sr0[TPB], sr1[TPB];
    __shared__ int    s_last;

    const int part = blockIdx.z;
    const int dir  = blockIdx.y;
    const int tile = blockIdx.x >> 1;
    const int half = blockIdx.x & 1;
    const int tid  = threadIdx.x;
    const int dp   = dir + 2 * part;
    const int qA   = tile * QTILE + tid;          // first query
    const int qB   = qA + TPB;                    // second query

    // --- per-block transform setup (thread 0; tiny) ---
    if (tid == 0) {
        float qa = quat[0], qb = quat[1], qc = quat[2], qd = quat[3];
        float qn = sqrtf(qa*qa + qb*qb + qc*qc + qd*qd);
        qa /= qn; qb /= qn; qc /= qn; qd /= qn;

        float B[16];
        B[0]  = 1.f - 2.f*qc*qc - 2.f*qd*qd;  B[1]  = 2.f*qb*qc - 2.f*qa*qd;        B[2]  = 2.f*qa*qc + 2.f*qb*qd;        B[3]  = bt[0];
        B[4]  = 2.f*qb*qc + 2.f*qa*qd;        B[5]  = 1.f - 2.f*qb*qb - 2.f*qd*qd;  B[6]  = 2.f*qc*qd - 2.f*qa*qb;        B[7]  = bt[1];
        B[8]  = 2.f*qb*qd - 2.f*qa*qc;        B[9]  = 2.f*qa*qb + 2.f*qc*qd;        B[10] = 1.f - 2.f*qb*qb - 2.f*qc*qc;  B[11] = bt[2];
        B[12] = 0.f; B[13] = 0.f; B[14] = 0.f; B[15] = 1.f;

        float ax = xyz[0], ay = xyz[1], az = xyz[2];
        float u  = rpy[0], v  = rpy[1], w  = rpy[2];
        float th = theta[0];
        float co = cosf(th), si = sinf(th), omc = 1.f - co;

        float R[16];
        R[0]  = u*u + (v*v + w*w)*co;   R[1]  = u*v*omc - w*si;          R[2]  = u*w*omc + v*si;
        R[3]  = (ax*(v*v + w*w) - u*(ay*v + az*w))*omc + (ay*w - az*v)*si;
        R[4]  = u*v*omc + w*si;         R[5]  = v*v + (u*u + w*w)*co;    R[6]  = v*w*omc - u*si;
        R[7]  = (ay*(u*u + w*w) - v*(ax*u + az*w))*omc + (az*u - ax*w)*si;
        R[8]  = u*w*omc - v*si;         R[9]  = v*w*omc + u*si;          R[10] = w*w + (u*u + v*v)*co;
        R[11] = (az*(u*u + v*v) - w*(ax*u + ay*v))*omc + (ax*v - ay*u)*si;
        R[12] = 0.f; R[13] = 0.f; R[14] = 0.f; R[15] = 1.f;

        float T[16];
        #pragma unroll
        for (int r = 0; r < 4; r++)
            #pragma unroll
            for (int c = 0; c < 4; c++) {
                float s = 0.f;
                #pragma unroll
                for (int k = 0; k < 4; k++) s += R[r*4 + k] * B[k*4 + c];
                T[r*4 + c] = s;
            }

        const float* X = (part == 0) ? B : T;
        #pragma unroll
        for (int i = 0; i < 12; i++) sxf[i] = X[i];

        if (blockIdx.x == 0 && dir == 0 && part == 0) {
            // out: [0]=all, [1]=base_obj, [2]=child_obj, [3..18]=base_T, [19..34]=rel_T
            #pragma unroll
            for (int i = 0; i < 16; i++) { out[3 + i] = B[i]; out[19 + i] = R[i]; }
        }
    }
    __syncthreads();

    const float t0 = sxf[0], t1 = sxf[1], t2  = sxf[2],  t3  = sxf[3];
    const float t4 = sxf[4], t5 = sxf[5], t6  = sxf[6],  t7  = sxf[7];
    const float t8 = sxf[8], t9 = sxf[9], t10 = sxf[10], t11 = sxf[11];

    const float* camP = cam + part * NPTS * 3;
    const float* cadP = cad + part * NPTS * 3;

    // --- load the two queries ---
    float qnA, qnB;
    unsigned long long qxA2, qyA2, qzA2, qxB2, qyB2, qzB2;
    {
        const float* src = (dir == 0) ? cadP : camP;
        float x = src[3*qA], y = src[3*qA + 1], z = src[3*qA + 2];
        float gx, gy, gz;
        if (dir == 0) {
            gx = t0*x + t1*y + t2*z  + t3;
            gy = t4*x + t5*y + t6*z  + t7;
            gz = t8*x + t9*y + t10*z + t11;
        } else { gx = x; gy = y; gz = z; }
        qnA = gx*gx + gy*gy + gz*gz;
        qxA2 = pack2(gx, gx); qyA2 = pack2(gy, gy); qzA2 = pack2(gz, gz);

        x = src[3*qB]; y = src[3*qB + 1]; z = src[3*qB + 2];
        if (dir == 0) {
            gx = t0*x + t1*y + t2*z  + t3;
            gy = t4*x + t5*y + t6*z  + t7;
            gz = t8*x + t9*y + t10*z + t11;
        } else { gx = x; gy = y; gz = z; }
        qnB = gx*gx + gy*gy + gz*gz;
        qxB2 = pack2(gx, gx); qyB2 = pack2(gy, gy); qzB2 = pack2(gz, gz);
    }

    float mA0 = 3.4e38f, mA1 = 3.4e38f, mB0 = 3.4e38f, mB1 = 3.4e38f;

    for (int ch = 0; ch < HALFPTS / CHUNK; ch++) {
        __syncthreads();
        // stage 2 db points per slot, -2 pre-folded into coords
        for (int jp = tid; jp < CHUNK / 2; jp += TPB) {
            int g0 = half * HALFPTS + ch * CHUNK + 2 * jp;
            float x0, y0, z0, x1, y1, z1;
            if (dir == 0) {
                x0 = camP[3*g0];     y0 = camP[3*g0 + 1]; z0 = camP[3*g0 + 2];
                x1 = camP[3*g0 + 3]; y1 = camP[3*g0 + 4]; z1 = camP[3*g0 + 5];
            } else {
                float a0 = cadP[3*g0],     b0 = cadP[3*g0 + 1], c0 = cadP[3*g0 + 2];
                float a1 = cadP[3*g0 + 3], b1 = cadP[3*g0 + 4], c1 = cadP[3*g0 + 5];
                x0 = t0*a0 + t1*b0 + t2*c0  + t3;   x1 = t0*a1 + t1*b1 + t2*c1  + t3;
                y0 = t4*a0 + t5*b0 + t6*c0  + t7;   y1 = t4*a1 + t5*b1 + t6*c1  + t7;
                z0 = t8*a0 + t9*b0 + t10*c0 + t11;  z1 = t8*a1 + t9*b1 + t10*c1 + t11;
            }
            float w0 = x0*x0 + y0*y0 + z0*z0;
            float w1 = x1*x1 + y1*y1 + z1*z1;
            sxy[jp] = make_float4(-2.f*x0, -2.f*x1, -2.f*y0, -2.f*y1);
            szw[jp] = make_float4(-2.f*z0, -2.f*z1,  w0,      w1);
        }
        __syncthreads();

        #pragma unroll 8
        for (int i = 0; i < CHUNK / 2; i++) {
            ulonglong2 a = *reinterpret_cast<const ulonglong2*>(&sxy[i]); // a.x=xp, a.y=yp
            ulonglong2 b = *reinterpret_cast<const ulonglong2*>(&szw[i]); // b.x=zp, b.y=wp
            unsigned long long tA = fma2(qzA2, b.x, b.y);
            unsigned long long tB = fma2(qzB2, b.x, b.y);
            tA = fma2(qyA2, a.y, tA);
            tB = fma2(qyB2, a.y, tB);
            tA = fma2(qxA2, a.x, tA);
            tB = fma2(qxB2, a.x, tB);
            unsigned int lo, hi;
            asm("mov.b64 {%0, %1}, %2;" : "=r"(lo), "=r"(hi) : "l"(tA));
            mA0 = fminf(mA0, __uint_as_float(lo));
            mA1 = fminf(mA1, __uint_as_float(hi));
            asm("mov.b64 {%0, %1}, %2;" : "=r"(lo), "=r"(hi) : "l"(tB));
            mB0 = fminf(mB0, __uint_as_float(lo));
            mB1 = fminf(mB1, __uint_as_float(hi));
        }
    }

    // partial results (can be tiny-negative; clamped in tail)
    g_pmin[dp][half][qA] = qnA + fminf(mA0, mA1);
    g_pmin[dp][half][qB] = qnB + fminf(mB0, mB1);

    // --- ticket: last block reduces everything ---
    __threadfence();
    if (tid == 0) {
        unsigned int ticket = atomicAdd(&g_count, 1u);
        s_last = (ticket == NBLK - 1) ? 1 : 0;
    }
    __syncthreads();
    if (!s_last) return;

    __threadfence();
    double a0 = 0.0, a1 = 0.0;
    for (int i = tid; i < 4 * NPTS; i += TPB) {
        const int d  = i >> 13;          // dp
        const int qq = i & (NPTS - 1);
        float v = fminf(g_pmin[d][0][qq], g_pmin[d][1][qq]);
        double dd = (double)sqrtf(fmaxf(v, 0.f));
        if (d < 2) a0 += dd; else a1 += dd;
    }
    sr0[tid] = a0; sr1[tid] = a1;
    __syncthreads();
    for (int s = TPB / 2; s > 0; s >>= 1) {
        if (tid < s) { sr0[tid] += sr0[tid + s]; sr1[tid] += sr1[tid + s]; }
        __syncthreads();
    }
    if (tid == 0) {
        double obj0 = sr0[0] / (double)NPTS;   // base part
        double obj1 = sr1[0] / (double)NPTS;   // child part
        out[1] = (float)obj0;
        out[2] = (float)obj1;
        out[0] = (float)(((double)pw[0] * obj0 + (double)pw[1] * obj1) / 2.0);
        g_count = 0;   // reset for next graph replay
    }
}

// ---------------------------------------------------------------------------
extern "C" void kernel_launch(void* const* d_in, const int* in_sizes, int n_in,
                              void* d_out, int out_size)
{
    const float* cam  = (const float*)d_in[0];  // camera_pts [2,8192,3]
    const float* cad  = (const float*)d_in[1];  // cad_pts    [2,8192,3]
    const float* xyz  = (const float*)d_in[2];  // [1,3]
    const float* rpy  = (const float*)d_in[3];  // [1,3]
    const float* pw   = (const float*)d_in[4];  // [2]
    const float* quat = (const float*)d_in[5];  // [4]
    const float* bt   = (const float*)d_in[6];  // [3,1]
    const float* th   = (const float*)d_in[7];  // [1]
    float* out = (float*)d_out;

    dim3 grid(NTILE * NHALF, 2, 2);   // 128 blocks (R6's proven shape)
    k_fused<<<grid, TPB>>>(cam, cad, xyz, rpy, quat, bt, th, pw, out);
}

// round 10
// speedup vs baseline: 1.3690x; 1.0449x over previous
#include <cuda_runtime.h>
#include <math.h>

#define NPTS    8192
#define TPB     256
#define QPT     2               // queries per thread (packed f32x2 broadcast)
#define QTILE   (TPB*QPT)       // 512 queries per block
#define NTILE   (NPTS/QTILE)    // 16
#define NHALF   2               // db split
#define HALFPTS (NPTS/NHALF)    // 4096
#define CHUNK   2048
#define NBLK    (NTILE*NHALF*4) // 128 blocks

// Scratch (no allocs allowed)
__device__ float        g_pmin[4][NHALF][NPTS]; // [dir+2*part][half][query] = qnorm+min
__device__ unsigned int g_count;                // zero-init; tail resets -> replay-safe

__device__ __forceinline__ unsigned long long pack2(float lo, float hi) {
    unsigned long long r;
    asm("mov.b64 %0, {%1, %2};" : "=l"(r)
        : "r"(__float_as_uint(lo)), "r"(__float_as_uint(hi)));
    return r;
}
__device__ __forceinline__ unsigned long long fma2(unsigned long long a,
                                                   unsigned long long b,
                                                   unsigned long long c) {
    unsigned long long d;
    asm("fma.rn.f32x2 %0, %1, %2, %3;" : "=l"(d) : "l"(a), "l"(b), "l"(c));
    return d;
}

// ---------------------------------------------------------------------------
// grid (NTILE*NHALF, dir, part) = 128 blocks of 256 thr (1/SM).
// Each thread owns 2 queries packed as broadcast f32x2. Inner loop processes
// 4 smem slots (8 db points) per group: all 8 LDS.128 issued up front (MLP=8,
// hides the 29-cyc LDS latency that ptxas left exposed in R9), then 4
// independent FFMA2 chains. 0.5 LDS per (query,point) pair.
// dir0: query = T@cad, db = cam.  dir1: query = cam, db = T@cad.
// min_j |q-y|^2 = |q|^2 + min_j(|y|^2 - 2 q.y); -2 folded into staged coords.
// Ticket-elected last block merges db halves -> sqrt -> fp64 means.
// ---------------------------------------------------------------------------
__global__ void __launch_bounds__(TPB)
k_fused(const float* __restrict__ cam, const float* __restrict__ cad,
        const float* __restrict__ xyz, const float* __restrict__ rpy,
        const float* __restrict__ quat, const float* __restrict__ bt,
        const float* __restrict__ theta, const float* __restrict__ pw,
        float* __restrict__ out)
{
    __shared__ float4 sxy[CHUNK / 2];   // (-2x0,-2x1,-2y0,-2y1)
    __shared__ float4 szw[CHUNK / 2];   // (-2z0,-2z1,  w0,  w1)
    __shared__ float  sxf[12];
    __shared__ double sr0[TPB], sr1[TPB];
    __shared__ int    s_last;

    const int part = blockIdx.z;
    const int dir  = blockIdx.y;
    const int tile = blockIdx.x >> 1;
    const int half = blockIdx.x & 1;
    const int tid  = threadIdx.x;
    const int dp   = dir + 2 * part;
    const int qA   = tile * QTILE + tid;          // first query
    const int qB   = qA + TPB;                    // second query

    // --- per-block transform setup (thread 0; tiny) ---
    if (tid == 0) {
        float qa = quat[0], qb = quat[1], qc = quat[2], qd = quat[3];
        float qn = sqrtf(qa*qa + qb*qb + qc*qc + qd*qd);
        qa /= qn; qb /= qn; qc /= qn; qd /= qn;

        float B[16];
        B[0]  = 1.f - 2.f*qc*qc - 2.f*qd*qd;  B[1]  = 2.f*qb*qc - 2.f*qa*qd;        B[2]  = 2.f*qa*qc + 2.f*qb*qd;        B[3]  = bt[0];
        B[4]  = 2.f*qb*qc + 2.f*qa*qd;        B[5]  = 1.f - 2.f*qb*qb - 2.f*qd*qd;  B[6]  = 2.f*qc*qd - 2.f*qa*qb;        B[7]  = bt[1];
        B[8]  = 2.f*qb*qd - 2.f*qa*qc;        B[9]  = 2.f*qa*qb + 2.f*qc*qd;        B[10] = 1.f - 2.f*qb*qb - 2.f*qc*qc;  B[11] = bt[2];
        B[12] = 0.f; B[13] = 0.f; B[14] = 0.f; B[15] = 1.f;

        float ax = xyz[0], ay = xyz[1], az = xyz[2];
        float u  = rpy[0], v  = rpy[1], w  = rpy[2];
        float th = theta[0];
        float co = cosf(th), si = sinf(th), omc = 1.f - co;

        float R[16];
        R[0]  = u*u + (v*v + w*w)*co;   R[1]  = u*v*omc - w*si;          R[2]  = u*w*omc + v*si;
        R[3]  = (ax*(v*v + w*w) - u*(ay*v + az*w))*omc + (ay*w - az*v)*si;
        R[4]  = u*v*omc + w*si;         R[5]  = v*v + (u*u + w*w)*co;    R[6]  = v*w*omc - u*si;
        R[7]  = (ay*(u*u + w*w) - v*(ax*u + az*w))*omc + (az*u - ax*w)*si;
        R[8]  = u*w*omc - v*si;         R[9]  = v*w*omc + u*si;          R[10] = w*w + (u*u + v*v)*co;
        R[11] = (az*(u*u + v*v) - w*(ax*u + ay*v))*omc + (ax*v - ay*u)*si;
        R[12] = 0.f; R[13] = 0.f; R[14] = 0.f; R[15] = 1.f;

        float T[16];
        #pragma unroll
        for (int r = 0; r < 4; r++)
            #pragma unroll
            for (int c = 0; c < 4; c++) {
                float s = 0.f;
                #pragma unroll
                for (int k = 0; k < 4; k++) s += R[r*4 + k] * B[k*4 + c];
                T[r*4 + c] = s;
            }

        const float* X = (part == 0) ? B : T;
        #pragma unroll
        for (int i = 0; i < 12; i++) sxf[i] = X[i];

        if (blockIdx.x == 0 && dir == 0 && part == 0) {
            // out: [0]=all, [1]=base_obj, [2]=child_obj, [3..18]=base_T, [19..34]=rel_T
            #pragma unroll
            for (int i = 0; i < 16; i++) { out[3 + i] = B[i]; out[19 + i] = R[i]; }
        }
    }
    __syncthreads();

    const float t0 = sxf[0], t1 = sxf[1], t2  = sxf[2],  t3  = sxf[3];
    const float t4 = sxf[4], t5 = sxf[5], t6  = sxf[6],  t7  = sxf[7];
    const float t8 = sxf[8], t9 = sxf[9], t10 = sxf[10], t11 = sxf[11];

    const float* camP = cam + part * NPTS * 3;
    const float* cadP = cad + part * NPTS * 3;

    // --- load the two queries ---
    float qnA, qnB;
    unsigned long long qxA2, qyA2, qzA2, qxB2, qyB2, qzB2;
    {
        const float* src = (dir == 0) ? cadP : camP;
        float x = src[3*qA], y = src[3*qA + 1], z = src[3*qA + 2];
        float gx, gy, gz;
        if (dir == 0) {
            gx = t0*x + t1*y + t2*z  + t3;
            gy = t4*x + t5*y + t6*z  + t7;
            gz = t8*x + t9*y + t10*z + t11;
        } else { gx = x; gy = y; gz = z; }
        qnA = gx*gx + gy*gy + gz*gz;
        qxA2 = pack2(gx, gx); qyA2 = pack2(gy, gy); qzA2 = pack2(gz, gz);

        x = src[3*qB]; y = src[3*qB + 1]; z = src[3*qB + 2];
        if (dir == 0) {
            gx = t0*x + t1*y + t2*z  + t3;
            gy = t4*x + t5*y + t6*z  + t7;
            gz = t8*x + t9*y + t10*z + t11;
        } else { gx = x; gy = y; gz = z; }
        qnB = gx*gx + gy*gy + gz*gz;
        qxB2 = pack2(gx, gx); qyB2 = pack2(gy, gy); qzB2 = pack2(gz, gz);
    }

    float mA0 = 3.4e38f, mA1 = 3.4e38f, mB0 = 3.4e38f, mB1 = 3.4e38f;

    for (int ch = 0; ch < HALFPTS / CHUNK; ch++) {
        __syncthreads();
        // stage 2 db points per slot, -2 pre-folded into coords
        for (int jp = tid; jp < CHUNK / 2; jp += TPB) {
            int g0 = half * HALFPTS + ch * CHUNK + 2 * jp;
            float x0, y0, z0, x1, y1, z1;
            if (dir == 0) {
                x0 = camP[3*g0];     y0 = camP[3*g0 + 1]; z0 = camP[3*g0 + 2];
                x1 = camP[3*g0 + 3]; y1 = camP[3*g0 + 4]; z1 = camP[3*g0 + 5];
            } else {
                float a0 = cadP[3*g0],     b0 = cadP[3*g0 + 1], c0 = cadP[3*g0 + 2];
                float a1 = cadP[3*g0 + 3], b1 = cadP[3*g0 + 4], c1 = cadP[3*g0 + 5];
                x0 = t0*a0 + t1*b0 + t2*c0  + t3;   x1 = t0*a1 + t1*b1 + t2*c1  + t3;
                y0 = t4*a0 + t5*b0 + t6*c0  + t7;   y1 = t4*a1 + t5*b1 + t6*c1  + t7;
                z0 = t8*a0 + t9*b0 + t10*c0 + t11;  z1 = t8*a1 + t9*b1 + t10*c1 + t11;
            }
            float w0 = x0*x0 + y0*y0 + z0*z0;
            float w1 = x1*x1 + y1*y1 + z1*z1;
            sxy[jp] = make_float4(-2.f*x0, -2.f*x1, -2.f*y0, -2.f*y1);
            szw[jp] = make_float4(-2.f*z0, -2.f*z1,  w0,      w1);
        }
        __syncthreads();

        // Manually pipelined: batch 8 LDS.128 (4 slots) up front, then compute.
        #pragma unroll 2
        for (int i = 0; i < CHUNK / 2; i += 4) {
            ulonglong2 av[4], bv[4];
            #pragma unroll
            for (int u = 0; u < 4; u++) {
                av[u] = *reinterpret_cast<const ulonglong2*>(&sxy[i + u]);
                bv[u] = *reinterpret_cast<const ulonglong2*>(&szw[i + u]);
            }
            #pragma unroll
            for (int u = 0; u < 4; u++) {
                unsigned long long tA = fma2(qzA2, bv[u].x, bv[u].y);
                unsigned long long tB = fma2(qzB2, bv[u].x, bv[u].y);
                tA = fma2(qyA2, av[u].y, tA);
                tB = fma2(qyB2, av[u].y, tB);
                tA = fma2(qxA2, av[u].x, tA);
                tB = fma2(qxB2, av[u].x, tB);
                unsigned int lo, hi;
                asm("mov.b64 {%0, %1}, %2;" : "=r"(lo), "=r"(hi) : "l"(tA));
                mA0 = fminf(mA0, __uint_as_float(lo));
                mA1 = fminf(mA1, __uint_as_float(hi));
                asm("mov.b64 {%0, %1}, %2;" : "=r"(lo), "=r"(hi) : "l"(tB));
                mB0 = fminf(mB0, __uint_as_float(lo));
                mB1 = fminf(mB1, __uint_as_float(hi));
            }
        }
    }

    // partial results (can be tiny-negative; clamped in tail)
    g_pmin[dp][half][qA] = qnA + fminf(mA0, mA1);
    g_pmin[dp][half][qB] = qnB + fminf(mB0, mB1);

    // --- ticket: last block reduces everything ---
    __threadfence();
    if (tid == 0) {
        unsigned int ticket = atomicAdd(&g_count, 1u);
        s_last = (ticket == NBLK - 1) ? 1 : 0;
    }
    __syncthreads();
    if (!s_last) return;

    __threadfence();
    double a0 = 0.0, a1 = 0.0;
    for (int i = tid; i < 4 * NPTS; i += TPB) {
        const int d  = i >> 13;          // dp
        const int qq = i & (NPTS - 1);
        float v = fminf(g_pmin[d][0][qq], g_pmin[d][1][qq]);
        double dd = (double)sqrtf(fmaxf(v, 0.f));
        if (d < 2) a0 += dd; else a1 += dd;
    }
    sr0[tid] = a0; sr1[tid] = a1;
    __syncthreads();
    for (int s = TPB / 2; s > 0; s >>= 1) {
        if (tid < s) { sr0[tid] += sr0[tid + s]; sr1[tid] += sr1[tid + s]; }
        __syncthreads();
    }
    if (tid == 0) {
        double obj0 = sr0[0] / (double)NPTS;   // base part
        double obj1 = sr1[0] / (double)NPTS;   // child part
        out[1] = (float)obj0;
        out[2] = (float)obj1;
        out[0] = (float)(((double)pw[0] * obj0 + (double)pw[1] * obj1) / 2.0);
        g_count = 0;   // reset for next graph replay
    }
}

// ---------------------------------------------------------------------------
extern "C" void kernel_launch(void* const* d_in, const int* in_sizes, int n_in,
                              void* d_out, int out_size)
{
    const float* cam  = (const float*)d_in[0];  // camera_pts [2,8192,3]
    const float* cad  = (const float*)d_in[1];  // cad_pts    [2,8192,3]
    const float* xyz  = (const float*)d_in[2];  // [1,3]
    const float* rpy  = (const float*)d_in[3];  // [1,3]
    const float* pw   = (const float*)d_in[4];  // [2]
    const float* quat = (const float*)d_in[5];  // [4]
    const float* bt   = (const float*)d_in[6];  // [3,1]
    const float* th   = (const float*)d_in[7];  // [1]
    float* out = (float*)d_out;

    dim3 grid(NTILE * NHALF, 2, 2);   // 128 blocks (1 per SM)
    k_fused<<<grid, TPB>>>(cam, cad, xyz, rpy, quat, bt, th, pw, out);
}

// round 11
// speedup vs baseline: 1.6181x; 1.1819x over previous
#include <cuda_runtime.h>
#include <math.h>

#define NPTS   8192
#define TPB    256
#define QPT    8                 // queries per thread (registers)
#define QTILE  (TPB*QPT)         // 2048 queries per block
#define NTILE  (NPTS/QTILE)      // 4
#define NSEG   8                 // db segments
#define SEGPTS (NPTS/NSEG)       // 1024
#define NBLK   (NTILE*NSEG*4)    // 128 blocks

// Scratch (no allocs allowed)
__device__ float        g_pmin[4][NSEG][NPTS]; // [dir+2*part][seg][query] = qnorm+min
__device__ unsigned int g_count;               // zero-init; tail resets -> replay-safe

// ---------------------------------------------------------------------------
// grid (NTILE*NSEG, dir, part) = 128 blocks of 256 thr (1/SM, 2 warps/SMSP).
// Each thread holds 8 queries in registers; each smem read (1 broadcast
// LDS.128) feeds 8 (query,point) pairs -> LDS is negligible; kernel is
// fma-pipe bound (3 FFMA/pair, FMNMX overlaps on alu pipe).
// dir0: query = T@cad, db = cam.  dir1: query = cam, db = T@cad.
// min_j |q-y|^2 = |q|^2 + min_j(|y|^2 - 2 q.y); -2 folded into staged coords.
// Ticket-elected last block merges db segments -> sqrt -> fp64 means.
// ---------------------------------------------------------------------------
__global__ void __launch_bounds__(TPB)
k_fused(const float* __restrict__ cam, const float* __restrict__ cad,
        const float* __restrict__ xyz, const float* __restrict__ rpy,
        const float* __restrict__ quat, const float* __restrict__ bt,
        const float* __restrict__ theta, const float* __restrict__ pw,
        float* __restrict__ out)
{
    __shared__ float4 sdb[SEGPTS];      // (-2x, -2y, -2z, |y|^2)
    __shared__ float  sxf[12];
    __shared__ double sr0[TPB], sr1[TPB];
    __shared__ int    s_last;

    const int part = blockIdx.z;
    const int dir  = blockIdx.y;
    const int tile = blockIdx.x >> 3;     // 0..3
    const int seg  = blockIdx.x & 7;      // 0..7
    const int tid  = threadIdx.x;
    const int dp   = dir + 2 * part;

    // --- per-block transform setup (thread 0; tiny) ---
    if (tid == 0) {
        float qa = quat[0], qb = quat[1], qc = quat[2], qd = quat[3];
        float qn = sqrtf(qa*qa + qb*qb + qc*qc + qd*qd);
        qa /= qn; qb /= qn; qc /= qn; qd /= qn;

        float B[16];
        B[0]  = 1.f - 2.f*qc*qc - 2.f*qd*qd;  B[1]  = 2.f*qb*qc - 2.f*qa*qd;        B[2]  = 2.f*qa*qc + 2.f*qb*qd;        B[3]  = bt[0];
        B[4]  = 2.f*qb*qc + 2.f*qa*qd;        B[5]  = 1.f - 2.f*qb*qb - 2.f*qd*qd;  B[6]  = 2.f*qc*qd - 2.f*qa*qb;        B[7]  = bt[1];
        B[8]  = 2.f*qb*qd - 2.f*qa*qc;        B[9]  = 2.f*qa*qb + 2.f*qc*qd;        B[10] = 1.f - 2.f*qb*qb - 2.f*qc*qc;  B[11] = bt[2];
        B[12] = 0.f; B[13] = 0.f; B[14] = 0.f; B[15] = 1.f;

        float ax = xyz[0], ay = xyz[1], az = xyz[2];
        float u  = rpy[0], v  = rpy[1], w  = rpy[2];
        float th = theta[0];
        float co = cosf(th), si = sinf(th), omc = 1.f - co;

        float R[16];
        R[0]  = u*u + (v*v + w*w)*co;   R[1]  = u*v*omc - w*si;          R[2]  = u*w*omc + v*si;
        R[3]  = (ax*(v*v + w*w) - u*(ay*v + az*w))*omc + (ay*w - az*v)*si;
        R[4]  = u*v*omc + w*si;         R[5]  = v*v + (u*u + w*w)*co;    R[6]  = v*w*omc - u*si;
        R[7]  = (ay*(u*u + w*w) - v*(ax*u + az*w))*omc + (az*u - ax*w)*si;
        R[8]  = u*w*omc - v*si;         R[9]  = v*w*omc + u*si;          R[10] = w*w + (u*u + v*v)*co;
        R[11] = (az*(u*u + v*v) - w*(ax*u + ay*v))*omc + (ax*v - ay*u)*si;
        R[12] = 0.f; R[13] = 0.f; R[14] = 0.f; R[15] = 1.f;

        float T[16];
        #pragma unroll
        for (int r = 0; r < 4; r++)
            #pragma unroll
            for (int c = 0; c < 4; c++) {
                float s = 0.f;
                #pragma unroll
                for (int k = 0; k < 4; k++) s += R[r*4 + k] * B[k*4 + c];
                T[r*4 + c] = s;
            }

        const float* X = (part == 0) ? B : T;
        #pragma unroll
        for (int i = 0; i < 12; i++) sxf[i] = X[i];

        if (blockIdx.x == 0 && dir == 0 && part == 0) {
            // out: [0]=all, [1]=base_obj, [2]=child_obj, [3..18]=base_T, [19..34]=rel_T
            #pragma unroll
            for (int i = 0; i < 16; i++) { out[3 + i] = B[i]; out[19 + i] = R[i]; }
        }
    }
    __syncthreads();

    const float t0 = sxf[0], t1 = sxf[1], t2  = sxf[2],  t3  = sxf[3];
    const float t4 = sxf[4], t5 = sxf[5], t6  = sxf[6],  t7  = sxf[7];
    const float t8 = sxf[8], t9 = sxf[9], t10 = sxf[10], t11 = sxf[11];

    const float* camP = cam + part * NPTS * 3;
    const float* cadP = cad + part * NPTS * 3;

    // --- stage this block's db segment (-2 folded into coords) ---
    for (int j = tid; j < SEGPTS; j += TPB) {
        int gj = seg * SEGPTS + j;
        float x, y, z;
        if (dir == 0) {
            x = camP[3*gj]; y = camP[3*gj + 1]; z = camP[3*gj + 2];
        } else {
            float a = cadP[3*gj], b = cadP[3*gj + 1], c = cadP[3*gj + 2];
            x = t0*a + t1*b + t2*c  + t3;
            y = t4*a + t5*b + t6*c  + t7;
            z = t8*a + t9*b + t10*c + t11;
        }
        float w = x*x + y*y + z*z;
        sdb[j] = make_float4(-2.f*x, -2.f*y, -2.f*z, w);
    }

    // --- load 8 queries into registers ---
    float qx[QPT], qy[QPT], qz[QPT], qn[QPT], m[QPT];
    #pragma unroll
    for (int k = 0; k < QPT; k++) {
        const int q = tile * QTILE + k * TPB + tid;
        const float* src = (dir == 0) ? cadP : camP;
        float x = src[3*q], y = src[3*q + 1], z = src[3*q + 2];
        if (dir == 0) {
            qx[k] = t0*x + t1*y + t2*z  + t3;
            qy[k] = t4*x + t5*y + t6*z  + t7;
            qz[k] = t8*x + t9*y + t10*z + t11;
        } else { qx[k] = x; qy[k] = y; qz[k] = z; }
        qn[k] = qx[k]*qx[k] + qy[k]*qy[k] + qz[k]*qz[k];
        m[k]  = 3.4e38f;
    }
    __syncthreads();

    // --- main loop: 1 broadcast LDS.128 feeds 8 pairs ---
    #pragma unroll 4
    for (int j = 0; j < SEGPTS; j++) {
        const float4 p = sdb[j];
        #pragma unroll
        for (int k = 0; k < QPT; k++) {
            float t = fmaf(p.z, qz[k], p.w);
            t = fmaf(p.y, qy[k], t);
            t = fmaf(p.x, qx[k], t);
            m[k] = fminf(m[k], t);
        }
    }

    // partial results (can be tiny-negative; clamped in tail)
    #pragma unroll
    for (int k = 0; k < QPT; k++) {
        const int q = tile * QTILE + k * TPB + tid;
        g_pmin[dp][seg][q] = qn[k] + m[k];
    }

    // --- ticket: last block reduces everything ---
    __threadfence();
    if (tid == 0) {
        unsigned int ticket = atomicAdd(&g_count, 1u);
        s_last = (ticket == NBLK - 1) ? 1 : 0;
    }
    __syncthreads();
    if (!s_last) return;

    __threadfence();
    double a0 = 0.0, a1 = 0.0;
    const int NG = NPTS / 4;                 // float4 groups per (dp,seg)
    for (int i = tid; i < 4 * NG; i += TPB) {
        const int d  = i / NG;
        const int qg = i % NG;
        const float4* base = reinterpret_cast<const float4*>(&g_pmin[d][0][0]);
        float4 v = base[qg];
        #pragma unroll
        for (int s = 1; s < NSEG; s++) {
            float4 u = base[s * NG + qg];
            v.x = fminf(v.x, u.x); v.y = fminf(v.y, u.y);
            v.z = fminf(v.z, u.z); v.w = fminf(v.w, u.w);
        }
        double dd = (double)sqrtf(fmaxf(v.x, 0.f))
                  + (double)sqrtf(fmaxf(v.y, 0.f))
                  + (double)sqrtf(fmaxf(v.z, 0.f))
                  + (double)sqrtf(fmaxf(v.w, 0.f));
        if (d < 2) a0 += dd; else a1 += dd;
    }
    sr0[tid] = a0; sr1[tid] = a1;
    __syncthreads();
    for (int s = TPB / 2; s > 0; s >>= 1) {
        if (tid < s) { sr0[tid] += sr0[tid + s]; sr1[tid] += sr1[tid + s]; }
        __syncthreads();
    }
    if (tid == 0) {
        double obj0 = sr0[0] / (double)NPTS;   // base part
        double obj1 = sr1[0] / (double)NPTS;   // child part
        out[1] = (float)obj0;
        out[2] = (float)obj1;
        out[0] = (float)(((double)pw[0] * obj0 + (double)pw[1] * obj1) / 2.0);
        g_count = 0;   // reset for next graph replay
    }
}

// ---------------------------------------------------------------------------
extern "C" void kernel_launch(void* const* d_in, const int* in_sizes, int n_in,
                              void* d_out, int out_size)
{
    const float* cam  = (const float*)d_in[0];  // camera_pts [2,8192,3]
    const float* cad  = (const float*)d_in[1];  // cad_pts    [2,8192,3]
    const float* xyz  = (const float*)d_in[2];  // [1,3]
    const float* rpy  = (const float*)d_in[3];  // [1,3]
    const float* pw   = (const float*)d_in[4];  // [2]
    const float* quat = (const float*)d_in[5];  // [4]
    const float* bt   = (const float*)d_in[6];  // [3,1]
    const float* th   = (const float*)d_in[7];  // [1]
    float* out = (float*)d_out;

    dim3 grid(NTILE * NSEG, 2, 2);   // 128 blocks (1 per SM)
    k_fused<<<grid, TPB>>>(cam, cad, xyz, rpy, quat, bt, th, pw, out);
}

// round 12
// speedup vs baseline: 1.6788x; 1.0375x over previous
#include <cuda_runtime.h>
#include <math.h>

#define NPTS   8192
#define TPB    512
#define QPT    8                 // queries per thread (registers)
#define QTILE  (TPB*QPT)         // 4096 queries per block
#define NTILE  (NPTS/QTILE)      // 2
#define NSEG   16                // db segments
#define SEGPTS (NPTS/NSEG)       // 512
#define NBLK   (NTILE*NSEG*4)    // 128 blocks (1/SM)

// Scratch (no allocs allowed)
__device__ float        g_pmin[4][NSEG][NPTS]; // [dir+2*part][seg][query] = qnorm+min
__device__ unsigned int g_count;               // zero-init; tail resets -> replay-safe

// ---------------------------------------------------------------------------
// grid (NTILE*NSEG, dir, part) = 128 blocks of 512 thr (1/SM, 4 warps/SMSP).
// R11's proven loop: each thread holds 8 queries in registers; one broadcast
// LDS.128 feeds 8 (query,point) pairs; 4 issue slots per pair (3 FFMA on fma
// pipe + 1 FMNMX on alu pipe). R11 was issue-bound at 2 warps/SMSP (62%);
// 4 warps/SMSP covers the latency (LDS now too rare for the crossbar to bind).
// dir0: query = T@cad, db = cam.  dir1: query = cam, db = T@cad.
// min_j |q-y|^2 = |q|^2 + min_j(|y|^2 - 2 q.y); -2 folded into staged coords.
// Ticket-elected last block merges db segments -> sqrt -> fp64 means.
// ---------------------------------------------------------------------------
__global__ void __launch_bounds__(TPB)
k_fused(const float* __restrict__ cam, const float* __restrict__ cad,
        const float* __restrict__ xyz, const float* __restrict__ rpy,
        const float* __restrict__ quat, const float* __restrict__ bt,
        const float* __restrict__ theta, const float* __restrict__ pw,
        float* __restrict__ out)
{
    __shared__ float4 sdb[SEGPTS];      // (-2x, -2y, -2z, |y|^2)
    __shared__ float  sxf[12];
    __shared__ double sr0[TPB], sr1[TPB];
    __shared__ int    s_last;

    const int part = blockIdx.z;
    const int dir  = blockIdx.y;
    const int tile = blockIdx.x >> 4;     // 0..1
    const int seg  = blockIdx.x & 15;     // 0..15
    const int tid  = threadIdx.x;
    const int dp   = dir + 2 * part;

    // --- per-block transform setup (thread 0; tiny) ---
    if (tid == 0) {
        float qa = quat[0], qb = quat[1], qc = quat[2], qd = quat[3];
        float qn = sqrtf(qa*qa + qb*qb + qc*qc + qd*qd);
        qa /= qn; qb /= qn; qc /= qn; qd /= qn;

        float B[16];
        B[0]  = 1.f - 2.f*qc*qc - 2.f*qd*qd;  B[1]  = 2.f*qb*qc - 2.f*qa*qd;        B[2]  = 2.f*qa*qc + 2.f*qb*qd;        B[3]  = bt[0];
        B[4]  = 2.f*qb*qc + 2.f*qa*qd;        B[5]  = 1.f - 2.f*qb*qb - 2.f*qd*qd;  B[6]  = 2.f*qc*qd - 2.f*qa*qb;        B[7]  = bt[1];
        B[8]  = 2.f*qb*qd - 2.f*qa*qc;        B[9]  = 2.f*qa*qb + 2.f*qc*qd;        B[10] = 1.f - 2.f*qb*qb - 2.f*qc*qc;  B[11] = bt[2];
        B[12] = 0.f; B[13] = 0.f; B[14] = 0.f; B[15] = 1.f;

        float ax = xyz[0], ay = xyz[1], az = xyz[2];
        float u  = rpy[0], v  = rpy[1], w  = rpy[2];
        float th = theta[0];
        float co = cosf(th), si = sinf(th), omc = 1.f - co;

        float R[16];
        R[0]  = u*u + (v*v + w*w)*co;   R[1]  = u*v*omc - w*si;          R[2]  = u*w*omc + v*si;
        R[3]  = (ax*(v*v + w*w) - u*(ay*v + az*w))*omc + (ay*w - az*v)*si;
        R[4]  = u*v*omc + w*si;         R[5]  = v*v + (u*u + w*w)*co;    R[6]  = v*w*omc - u*si;
        R[7]  = (ay*(u*u + w*w) - v*(ax*u + az*w))*omc + (az*u - ax*w)*si;
        R[8]  = u*w*omc - v*si;         R[9]  = v*w*omc + u*si;          R[10] = w*w + (u*u + v*v)*co;
        R[11] = (az*(u*u + v*v) - w*(ax*u + ay*v))*omc + (ax*v - ay*u)*si;
        R[12] = 0.f; R[13] = 0.f; R[14] = 0.f; R[15] = 1.f;

        float T[16];
        #pragma unroll
        for (int r = 0; r < 4; r++)
            #pragma unroll
            for (int c = 0; c < 4; c++) {
                float s = 0.f;
                #pragma unroll
                for (int k = 0; k < 4; k++) s += R[r*4 + k] * B[k*4 + c];
                T[r*4 + c] = s;
            }

        const float* X = (part == 0) ? B : T;
        #pragma unroll
        for (int i = 0; i < 12; i++) sxf[i] = X[i];

        if (blockIdx.x == 0 && dir == 0 && part == 0) {
            // out: [0]=all, [1]=base_obj, [2]=child_obj, [3..18]=base_T, [19..34]=rel_T
            #pragma unroll
            for (int i = 0; i < 16; i++) { out[3 + i] = B[i]; out[19 + i] = R[i]; }
        }
    }
    __syncthreads();

    const float t0 = sxf[0], t1 = sxf[1], t2  = sxf[2],  t3  = sxf[3];
    const float t4 = sxf[4], t5 = sxf[5], t6  = sxf[6],  t7  = sxf[7];
    const float t8 = sxf[8], t9 = sxf[9], t10 = sxf[10], t11 = sxf[11];

    const float* camP = cam + part * NPTS * 3;
    const float* cadP = cad + part * NPTS * 3;

    // --- stage this block's db segment (-2 folded into coords) ---
    for (int j = tid; j < SEGPTS; j += TPB) {
        int gj = seg * SEGPTS + j;
        float x, y, z;
        if (dir == 0) {
            x = camP[3*gj]; y = camP[3*gj + 1]; z = camP[3*gj + 2];
        } else {
            float a = cadP[3*gj], b = cadP[3*gj + 1], c = cadP[3*gj + 2];
            x = t0*a + t1*b + t2*c  + t3;
            y = t4*a + t5*b + t6*c  + t7;
            z = t8*a + t9*b + t10*c + t11;
        }
        float w = x*x + y*y + z*z;
        sdb[j] = make_float4(-2.f*x, -2.f*y, -2.f*z, w);
    }

    // --- load 8 queries into registers ---
    float qx[QPT], qy[QPT], qz[QPT], qn[QPT], m[QPT];
    #pragma unroll
    for (int k = 0; k < QPT; k++) {
        const int q = tile * QTILE + k * TPB + tid;
        const float* src = (dir == 0) ? cadP : camP;
        float x = src[3*q], y = src[3*q + 1], z = src[3*q + 2];
        if (dir == 0) {
            qx[k] = t0*x + t1*y + t2*z  + t3;
            qy[k] = t4*x + t5*y + t6*z  + t7;
            qz[k] = t8*x + t9*y + t10*z + t11;
        } else { qx[k] = x; qy[k] = y; qz[k] = z; }
        qn[k] = qx[k]*qx[k] + qy[k]*qy[k] + qz[k]*qz[k];
        m[k]  = 3.4e38f;
    }
    __syncthreads();

    // --- main loop: 1 broadcast LDS.128 feeds 8 pairs ---
    #pragma unroll 4
    for (int j = 0; j < SEGPTS; j++) {
        const float4 p = sdb[j];
        #pragma unroll
        for (int k = 0; k < QPT; k++) {
            float t = fmaf(p.z, qz[k], p.w);
            t = fmaf(p.y, qy[k], t);
            t = fmaf(p.x, qx[k], t);
            m[k] = fminf(m[k], t);
        }
    }

    // partial results (can be tiny-negative; clamped in tail)
    #pragma unroll
    for (int k = 0; k < QPT; k++) {
        const int q = tile * QTILE + k * TPB + tid;
        g_pmin[dp][seg][q] = qn[k] + m[k];
    }

    // --- ticket: last block reduces everything ---
    __threadfence();
    if (tid == 0) {
        unsigned int ticket = atomicAdd(&g_count, 1u);
        s_last = (ticket == NBLK - 1) ? 1 : 0;
    }
    __syncthreads();
    if (!s_last) return;

    __threadfence();
    double a0 = 0.0, a1 = 0.0;
    const int NG = NPTS / 4;                 // float4 groups per (dp,seg)
    for (int i = tid; i < 4 * NG; i += TPB) {
        const int d  = i / NG;
        const int qg = i % NG;
        const float4* base = reinterpret_cast<const float4*>(&g_pmin[d][0][0]);
        float4 v = base[qg];
        #pragma unroll
        for (int s = 1; s < NSEG; s++) {
            float4 u = base[s * NG + qg];
            v.x = fminf(v.x, u.x); v.y = fminf(v.y, u.y);
            v.z = fminf(v.z, u.z); v.w = fminf(v.w, u.w);
        }
        double dd = (double)sqrtf(fmaxf(v.x, 0.f))
                  + (double)sqrtf(fmaxf(v.y, 0.f))
                  + (double)sqrtf(fmaxf(v.z, 0.f))
                  + (double)sqrtf(fmaxf(v.w, 0.f));
        if (d < 2) a0 += dd; else a1 += dd;
    }
    sr0[tid] = a0; sr1[tid] = a1;
    __syncthreads();
    for (int s = TPB / 2; s > 0; s >>= 1) {
        if (tid < s) { sr0[tid] += sr0[tid + s]; sr1[tid] += sr1[tid + s]; }
        __syncthreads();
    }
    if (tid == 0) {
        double obj0 = sr0[0] / (double)NPTS;   // base part
        double obj1 = sr1[0] / (double)NPTS;   // child part
        out[1] = (float)obj0;
        out[2] = (float)obj1;
        out[0] = (float)(((double)pw[0] * obj0 + (double)pw[1] * obj1) / 2.0);
        g_count = 0;   // reset for next graph replay
    }
}

// ---------------------------------------------------------------------------
extern "C" void kernel_launch(void* const* d_in, const int* in_sizes, int n_in,
                              void* d_out, int out_size)
{
    const float* cam  = (const float*)d_in[0];  // camera_pts [2,8192,3]
    const float* cad  = (const float*)d_in[1];  // cad_pts    [2,8192,3]
    const float* xyz  = (const float*)d_in[2];  // [1,3]
    const float* rpy  = (const float*)d_in[3];  // [1,3]
    const float* pw   = (const float*)d_in[4];  // [2]
    const float* quat = (const float*)d_in[5];  // [4]
    const float* bt   = (const float*)d_in[6];  // [3,1]
    const float* th   = (const float*)d_in[7];  // [1]
    float* out = (float*)d_out;

    dim3 grid(NTILE * NSEG, 2, 2);   // 128 blocks of 512 thr (1 per SM)
    k_fused<<<grid, TPB>>>(cam, cad, xyz, rpy, quat, bt, th, pw, out);
}

// round 13
// speedup vs baseline: 1.7556x; 1.0458x over previous
#include <cuda_runtime.h>
#include <math.h>

#define NPTS   8192
#define TPB    512
#define QPT    8                 // queries per thread (4 packed f32x2 pairs)
#define QTILE  (TPB*QPT)         // 4096 queries per block
#define NTILE  (NPTS/QTILE)      // 2
#define NSEG   16                // db segments
#define SEGPTS (NPTS/NSEG)       // 512
#define NBLK   (NTILE*NSEG*4)    // 128 blocks (1/SM)

// Scratch (no allocs allowed)
__device__ float        g_pmin[4][NSEG][NPTS]; // [dir+2*part][seg][query] = qnorm+min
__device__ unsigned int g_count;               // zero-init; tail resets -> replay-safe

__device__ __forceinline__ unsigned long long pack2(float lo, float hi) {
    unsigned long long r;
    asm("mov.b64 %0, {%1, %2};" : "=l"(r)
        : "r"(__float_as_uint(lo)), "r"(__float_as_uint(hi)));
    return r;
}
__device__ __forceinline__ unsigned long long fma2(unsigned long long a,
                                                   unsigned long long b,
                                                   unsigned long long c) {
    unsigned long long d;
    asm("fma.rn.f32x2 %0, %1, %2, %3;" : "=l"(d) : "l"(a), "l"(b), "l"(c));
    return d;
}

// ---------------------------------------------------------------------------
// grid (NTILE*NSEG, dir, part) = 128 blocks of 512 thr (1/SM, 4 warps/SMSP).
// R12 was at the FFMA-3reg rt=2 structural floor (24 scalar FFMA per thread
// per db point). This version packs QUERIES in f32x2 pairs: smem holds each
// db point duplicated ((-2x,-2x,-2y,-2y) / (-2z,-2z,w,w)); per db point each
// thread runs 4 independent FFMA2 chains (12 FFMA2 = 24 MACs) -> fma-pipe
// slots per pair halved vs R12. Same successful codegen shape as R6.
// dir0: query = T@cad, db = cam.  dir1: query = cam, db = T@cad.
// min_j |q-y|^2 = |q|^2 + min_j(|y|^2 - 2 q.y); -2 folded into staged coords.
// Ticket-elected last block merges db segments -> sqrt -> fp64 means.
// ---------------------------------------------------------------------------
__global__ void __launch_bounds__(TPB)
k_fused(const float* __restrict__ cam, const float* __restrict__ cad,
        const float* __restrict__ xyz, const float* __restrict__ rpy,
        const float* __restrict__ quat, const float* __restrict__ bt,
        const float* __restrict__ theta, const float* __restrict__ pw,
        float* __restrict__ out)
{
    __shared__ float4 sA[SEGPTS];       // (-2x, -2x, -2y, -2y)
    __shared__ float4 sB[SEGPTS];       // (-2z, -2z,  w,   w)
    __shared__ float  sxf[12];
    __shared__ double sr0[TPB], sr1[TPB];
    __shared__ int    s_last;

    const int part = blockIdx.z;
    const int dir  = blockIdx.y;
    const int tile = blockIdx.x >> 4;     // 0..1
    const int seg  = blockIdx.x & 15;     // 0..15
    const int tid  = threadIdx.x;
    const int dp   = dir + 2 * part;

    // --- per-block transform setup (thread 0; tiny) ---
    if (tid == 0) {
        float qa = quat[0], qb = quat[1], qc = quat[2], qd = quat[3];
        float qn = sqrtf(qa*qa + qb*qb + qc*qc + qd*qd);
        qa /= qn; qb /= qn; qc /= qn; qd /= qn;

        float B[16];
        B[0]  = 1.f - 2.f*qc*qc - 2.f*qd*qd;  B[1]  = 2.f*qb*qc - 2.f*qa*qd;        B[2]  = 2.f*qa*qc + 2.f*qb*qd;        B[3]  = bt[0];
        B[4]  = 2.f*qb*qc + 2.f*qa*qd;        B[5]  = 1.f - 2.f*qb*qb - 2.f*qd*qd;  B[6]  = 2.f*qc*qd - 2.f*qa*qb;        B[7]  = bt[1];
        B[8]  = 2.f*qb*qd - 2.f*qa*qc;        B[9]  = 2.f*qa*qb + 2.f*qc*qd;        B[10] = 1.f - 2.f*qb*qb - 2.f*qc*qc;  B[11] = bt[2];
        B[12] = 0.f; B[13] = 0.f; B[14] = 0.f; B[15] = 1.f;

        float ax = xyz[0], ay = xyz[1], az = xyz[2];
        float u  = rpy[0], v  = rpy[1], w  = rpy[2];
        float th = theta[0];
        float co = cosf(th), si = sinf(th), omc = 1.f - co;

        float R[16];
        R[0]  = u*u + (v*v + w*w)*co;   R[1]  = u*v*omc - w*si;          R[2]  = u*w*omc + v*si;
        R[3]  = (ax*(v*v + w*w) - u*(ay*v + az*w))*omc + (ay*w - az*v)*si;
        R[4]  = u*v*omc + w*si;         R[5]  = v*v + (u*u + w*w)*co;    R[6]  = v*w*omc - u*si;
        R[7]  = (ay*(u*u + w*w) - v*(ax*u + az*w))*omc + (az*u - ax*w)*si;
        R[8]  = u*w*omc - v*si;         R[9]  = v*w*omc + u*si;          R[10] = w*w + (u*u + v*v)*co;
        R[11] = (az*(u*u + v*v) - w*(ax*u + ay*v))*omc + (ax*v - ay*u)*si;
        R[12] = 0.f; R[13] = 0.f; R[14] = 0.f; R[15] = 1.f;

        float T[16];
        #pragma unroll
        for (int r = 0; r < 4; r++)
            #pragma unroll
            for (int c = 0; c < 4; c++) {
                float s = 0.f;
                #pragma unroll
                for (int k = 0; k < 4; k++) s += R[r*4 + k] * B[k*4 + c];
                T[r*4 + c] = s;
            }

        const float* X = (part == 0) ? B : T;
        #pragma unroll
        for (int i = 0; i < 12; i++) sxf[i] = X[i];

        if (blockIdx.x == 0 && dir == 0 && part == 0) {
            // out: [0]=all, [1]=base_obj, [2]=child_obj, [3..18]=base_T, [19..34]=rel_T
            #pragma unroll
            for (int i = 0; i < 16; i++) { out[3 + i] = B[i]; out[19 + i] = R[i]; }
        }
    }
    __syncthreads();

    const float t0 = sxf[0], t1 = sxf[1], t2  = sxf[2],  t3  = sxf[3];
    const float t4 = sxf[4], t5 = sxf[5], t6  = sxf[6],  t7  = sxf[7];
    const float t8 = sxf[8], t9 = sxf[9], t10 = sxf[10], t11 = sxf[11];

    const float* camP = cam + part * NPTS * 3;
    const float* cadP = cad + part * NPTS * 3;

    // --- stage this block's db segment, duplicated halves, -2 folded in ---
    for (int j = tid; j < SEGPTS; j += TPB) {
        int gj = seg * SEGPTS + j;
        float x, y, z;
        if (dir == 0) {
            x = camP[3*gj]; y = camP[3*gj + 1]; z = camP[3*gj + 2];
        } else {
            float a = cadP[3*gj], b = cadP[3*gj + 1], c = cadP[3*gj + 2];
            x = t0*a + t1*b + t2*c  + t3;
            y = t4*a + t5*b + t6*c  + t7;
            z = t8*a + t9*b + t10*c + t11;
        }
        float w  = x*x + y*y + z*z;
        float nx = -2.f*x, ny = -2.f*y, nz = -2.f*z;
        sA[j] = make_float4(nx, nx, ny, ny);
        sB[j] = make_float4(nz, nz, w,  w);
    }

    // --- load 8 queries, pack as 4 f32x2 pairs ---
    float qn[QPT], m[QPT];
    unsigned long long qx2[4], qy2[4], qz2[4];
    {
        float qx[QPT], qy[QPT], qz[QPT];
        #pragma unroll
        for (int k = 0; k < QPT; k++) {
            const int q = tile * QTILE + k * TPB + tid;
            const float* src = (dir == 0) ? cadP : camP;
            float x = src[3*q], y = src[3*q + 1], z = src[3*q + 2];
            if (dir == 0) {
                qx[k] = t0*x + t1*y + t2*z  + t3;
                qy[k] = t4*x + t5*y + t6*z  + t7;
                qz[k] = t8*x + t9*y + t10*z + t11;
            } else { qx[k] = x; qy[k] = y; qz[k] = z; }
            qn[k] = qx[k]*qx[k] + qy[k]*qy[k] + qz[k]*qz[k];
            m[k]  = 3.4e38f;
        }
        #pragma unroll
        for (int p = 0; p < 4; p++) {
            qx2[p] = pack2(qx[2*p], qx[2*p + 1]);
            qy2[p] = pack2(qy[2*p], qy[2*p + 1]);
            qz2[p] = pack2(qz[2*p], qz[2*p + 1]);
        }
    }
    __syncthreads();

    // --- main loop: 2 LDS.128 feed 8 (query,point) pairs via 4 FFMA2 chains ---
    #pragma unroll 4
    for (int j = 0; j < SEGPTS; j++) {
        const ulonglong2 A = *reinterpret_cast<const ulonglong2*>(&sA[j]); // A.x=xx, A.y=yy
        const ulonglong2 B = *reinterpret_cast<const ulonglong2*>(&sB[j]); // B.x=zz, B.y=ww
        #pragma unroll
        for (int p = 0; p < 4; p++) {
            unsigned long long t = fma2(qz2[p], B.x, B.y);
            t = fma2(qy2[p], A.y, t);
            t = fma2(qx2[p], A.x, t);
            unsigned int lo, hi;
            asm("mov.b64 {%0, %1}, %2;" : "=r"(lo), "=r"(hi) : "l"(t));
            m[2*p]     = fminf(m[2*p],     __uint_as_float(lo));
            m[2*p + 1] = fminf(m[2*p + 1], __uint_as_float(hi));
        }
    }

    // partial results (can be tiny-negative; clamped in tail)
    #pragma unroll
    for (int k = 0; k < QPT; k++) {
        const int q = tile * QTILE + k * TPB + tid;
        g_pmin[dp][seg][q] = qn[k] + m[k];
    }

    // --- ticket: last block reduces everything ---
    __threadfence();
    if (tid == 0) {
        unsigned int ticket = atomicAdd(&g_count, 1u);
        s_last = (ticket == NBLK - 1) ? 1 : 0;
    }
    __syncthreads();
    if (!s_last) return;

    __threadfence();
    double a0 = 0.0, a1 = 0.0;
    const int NG = NPTS / 4;                 // float4 groups per (dp,seg)
    for (int i = tid; i < 4 * NG; i += TPB) {
        const int d  = i / NG;
        const int qg = i % NG;
        const float4* base = reinterpret_cast<const float4*>(&g_pmin[d][0][0]);
        float4 v = base[qg];
        #pragma unroll
        for (int s = 1; s < NSEG; s++) {
            float4 u = base[s * NG + qg];
            v.x = fminf(v.x, u.x); v.y = fminf(v.y, u.y);
            v.z = fminf(v.z, u.z); v.w = fminf(v.w, u.w);
        }
        double dd = (double)sqrtf(fmaxf(v.x, 0.f))
                  + (double)sqrtf(fmaxf(v.y, 0.f))
                  + (double)sqrtf(fmaxf(v.z, 0.f))
                  + (double)sqrtf(fmaxf(v.w, 0.f));
        if (d < 2) a0 += dd; else a1 += dd;
    }
    sr0[tid] = a0; sr1[tid] = a1;
    __syncthreads();
    for (int s = TPB / 2; s > 0; s >>= 1) {
        if (tid < s) { sr0[tid] += sr0[tid + s]; sr1[tid] += sr1[tid + s]; }
        __syncthreads();
    }
    if (tid == 0) {
        double obj0 = sr0[0] / (double)NPTS;   // base part
        double obj1 = sr1[0] / (double)NPTS;   // child part
        out[1] = (float)obj0;
        out[2] = (float)obj1;
        out[0] = (float)(((double)pw[0] * obj0 + (double)pw[1] * obj1) / 2.0);
        g_count = 0;   // reset for next graph replay
    }
}

// ---------------------------------------------------------------------------
extern "C" void kernel_launch(void* const* d_in, const int* in_sizes, int n_in,
                              void* d_out, int out_size)
{
    const float* cam  = (const float*)d_in[0];  // camera_pts [2,8192,3]
    const float* cad  = (const float*)d_in[1];  // cad_pts    [2,8192,3]
    const float* xyz  = (const float*)d_in[2];  // [1,3]
    const float* rpy  = (const float*)d_in[3];  // [1,3]
    const float* pw   = (const float*)d_in[4];  // [2]
    const float* quat = (const float*)d_in[5];  // [4]
    const float* bt   = (const float*)d_in[6];  // [3,1]
    const float* th   = (const float*)d_in[7];  // [1]
    float* out = (float*)d_out;

    dim3 grid(NTILE * NSEG, 2, 2);   // 128 blocks of 512 thr (1 per SM)
    k_fused<<<grid, TPB>>>(cam, cad, xyz, rpy, quat, bt, th, pw, out);
}